// round 7
// baseline (speedup 1.0000x reference)
#include <cuda_runtime.h>
#include <cstdint>

// cAttend_simple collapsed algebraically:
//   out[b,j] = val[b,j] * (1 + SCALE*(w_b . embed[pos[b,j]] + c_b))
//   s_b = Wq u_b + bq V_b;  u_b = sum_i val[b,i] embed[pos[b,i]];  V_b = sum_i val[b,i]
//   w_b = Wk^T s_b;  c_b = s_b . bk
//
// Single persistent kernel, 128 blocks x 1024 threads (1 CTA/SM, co-resident).
// Phase 1 gathers embed rows into a smem row-cache via cp.async.bulk (async/TMA
// pipe, mbarrier completion); phase 3 reuses the cache (no 2nd global gather).

#define BB 4
#define NN 4096
#define EE 256
#define DD 64
#define NBLK 128           // persistent blocks (<=148 SMs -> all resident)
#define BPB  32            // blocks per batch
#define RPB  128           // rows per block
#define SCALE 0.125f       // 64^{-1/2}
#define ROW_BYTES 1024     // EE * 4

// smem layout (bytes)
#define OFF_SROW 0                       // float4 srow[RPB][64]   131072
#define OFF_SP   131072                  // int   sp[RPB]          512
#define OFF_SV   (131072 + 512)          // float sv[RPB]          512
#define OFF_RED  (131072 + 1024)         // float4 red[16][64]     16384 (reused as wpart[4][256])
#define OFF_U    (131072 + 1024 + 16384) // float u[256]           1024
#define OFF_S    (OFF_U + 1024)          // float s[64]            256
#define OFF_W    (OFF_S + 256)           // float wv[256]          1024
#define OFF_MISC (OFF_W + 1024)          // float misc[4]          16
#define OFF_MBAR (OFF_MISC + 16)         // uint64 mbar            16 (8 used)
#define SMEM_BYTES (OFF_MBAR + 16)       // ~150 KB (< 227 KB opt-in)

// Deterministic scratch (fixed-slot writes, fixed-order reads)
__device__ float4 g_part4[BB][BPB][EE / 4];
__device__ float  g_vpart[BB][BPB];
// Graph-replay-safe grid barrier state
__device__ unsigned g_cnt = 0;
__device__ unsigned g_gen = 0;

__device__ __forceinline__ float4 ldcg4(const float4* p) {
    float4 r;
    asm volatile("ld.global.cg.v4.f32 {%0,%1,%2,%3}, [%4];"
                 : "=f"(r.x), "=f"(r.y), "=f"(r.z), "=f"(r.w) : "l"(p));
    return r;
}

__device__ __forceinline__ void bulk_cp(uint32_t dst, const void* src,
                                        uint32_t bytes, uint32_t mbar) {
    asm volatile(
        "cp.async.bulk.shared::cta.global.mbarrier::complete_tx::bytes "
        "[%0], [%1], %2, [%3];"
        :: "r"(dst), "l"(src), "r"(bytes), "r"(mbar) : "memory");
}

__global__ void __launch_bounds__(1024, 1)
k_fused(const float* __restrict__ val, const int* __restrict__ pos,
        const float* __restrict__ embed, const float* __restrict__ Wq,
        const float* __restrict__ bq, const float* __restrict__ Wk,
        const float* __restrict__ bk, float* __restrict__ out) {
    const int blk  = blockIdx.x;
    const int b    = blk >> 5;        // batch
    const int ch   = blk & 31;        // chunk within batch
    const int t    = threadIdx.x;
    const int g    = t >> 6;          // 16 groups of 64 lanes
    const int l    = t & 63;
    const int warp = t >> 5;
    const int lane = t & 31;

    extern __shared__ char smem[];
    float4* srow = (float4*)(smem + OFF_SROW);   // [RPB][64]
    int*    sp   = (int*)   (smem + OFF_SP);
    float*  sv   = (float*) (smem + OFF_SV);
    float4* red  = (float4*)(smem + OFF_RED);    // [16][64]
    float*  wpart= (float*) (smem + OFF_RED);    // reuse as [4][256]
    float*  u    = (float*) (smem + OFF_U);
    float*  sd   = (float*) (smem + OFF_S);
    float*  wv   = (float*) (smem + OFF_W);
    float*  misc = (float*) (smem + OFF_MISC);   // [0]=V, [1]=c

    uint32_t smem_u32;
    {
        uint64_t tmp;
        asm("cvta.to.shared.u64 %0, %1;" : "=l"(tmp) : "l"(smem));
        smem_u32 = (uint32_t)tmp;
    }
    const uint32_t mbar = smem_u32 + OFF_MBAR;
    const uint32_t srow_base = smem_u32 + OFF_SROW;

    // Snapshot generation BEFORE this block can possibly arrive at the barrier.
    const unsigned gen0 = *(volatile unsigned*)&g_gen;

    if (t == 0) {
        asm volatile("mbarrier.init.shared.b64 [%0], 1;" :: "r"(mbar) : "memory");
        asm volatile("fence.proxy.async.shared::cta;" ::: "memory");
    }
    if (t < RPB) {
        sp[t] = pos[b * NN + ch * RPB + t];
        sv[t] = val[b * NN + ch * RPB + t];
    }
    __syncthreads();

    // ---- Phase 1: bulk-copy gather on the async/TMA pipe.
    // Warps 0..7, lane 0: 16 row-copies each (1 KB per row), one mbarrier.
    if (t == 0) {
        asm volatile("mbarrier.arrive.expect_tx.shared.b64 _, [%0], %1;"
                     :: "r"(mbar), "r"((uint32_t)(RPB * ROW_BYTES)) : "memory");
    }
    if (lane == 0 && warp < 8) {
#pragma unroll
        for (int i = 0; i < 16; i++) {
            const int r = warp * 16 + i;
            bulk_cp(srow_base + (uint32_t)r * ROW_BYTES,
                    embed + (size_t)sp[r] * EE, ROW_BYTES, mbar);
        }
    }

    // Overlap: V partial sum while copies are in flight
    if (t == 1023) {
        float s = 0.f;
#pragma unroll
        for (int i = 0; i < RPB; i++) s += sv[i];
        g_vpart[b][ch] = s;
    }

    // Wait for all 128 KB to land (all threads; HW-sleep try_wait loop)
    {
        uint32_t done;
        asm volatile(
            "{\n\t.reg .pred p;\n\t"
            "mbarrier.try_wait.parity.acquire.cta.shared::cta.b64 p, [%1], 0, 0x989680;\n\t"
            "selp.b32 %0, 1, 0, p;\n\t}"
            : "=r"(done) : "r"(mbar) : "memory");
        while (!done) {
            asm volatile(
                "{\n\t.reg .pred p;\n\t"
                "mbarrier.try_wait.parity.acquire.cta.shared::cta.b64 p, [%1], 0, 0x989680;\n\t"
                "selp.b32 %0, 1, 0, p;\n\t}"
                : "=r"(done) : "r"(mbar) : "memory");
        }
    }
    __syncthreads();

    // Weighted accumulate from the smem cache (LDS.128, pipelined)
    float4 acc = make_float4(0.f, 0.f, 0.f, 0.f);
#pragma unroll
    for (int i = 0; i < 8; i++) {
        const int r = g * 8 + i;
        const float4 a = srow[r * 64 + l];
        const float v = sv[r];
        acc.x += v * a.x; acc.y += v * a.y; acc.z += v * a.z; acc.w += v * a.w;
    }
    red[g * 64 + l] = acc;
    __syncthreads();

    if (t < 64) {
        float4 s0 = red[t];
#pragma unroll
        for (int j = 1; j < 16; j++) {
            const float4 r4 = red[j * 64 + t];
            s0.x += r4.x; s0.y += r4.y; s0.z += r4.z; s0.w += r4.w;
        }
        g_part4[b][ch][t] = s0;
    }

    // ---- Grid barrier (graph-replay safe: monotonic generation counter)
    __threadfence();
    __syncthreads();
    if (t == 0) {
        const unsigned my = atomicAdd(&g_cnt, 1);
        if (my == NBLK - 1) {
            g_cnt = 0;                   // all NBLK have arrived; safe to reset
            __threadfence();
            atomicAdd(&g_gen, 1);
        } else {
            while (*(volatile unsigned*)&g_gen == gen0) { __nanosleep(64); }
        }
        __threadfence();
    }
    __syncthreads();

    // ---- Phase 2 (redundant per block, for its own batch b)
    float4 a2 = make_float4(0.f, 0.f, 0.f, 0.f);
#pragma unroll
    for (int c = g; c < BPB; c += 16) {
        const float4 p4 = ldcg4(&g_part4[b][c][l]);
        a2.x += p4.x; a2.y += p4.y; a2.z += p4.z; a2.w += p4.w;
    }
    red[g * 64 + l] = a2;
    if (warp == 31) {
        float v = 0.f;
        if (lane < BPB) {
            asm volatile("ld.global.cg.f32 %0, [%1];" : "=f"(v) : "l"(&g_vpart[b][lane]));
        }
#pragma unroll
        for (int o = 16; o; o >>= 1) v += __shfl_xor_sync(0xffffffffu, v, o);
        if (lane == 0) misc[0] = v;
    }
    __syncthreads();

    if (t < 64) {
        float4 a = red[t];
#pragma unroll
        for (int j = 1; j < 16; j++) {
            const float4 r4 = red[j * 64 + t];
            a.x += r4.x; a.y += r4.y; a.z += r4.z; a.w += r4.w;
        }
        u[t * 4 + 0] = a.x; u[t * 4 + 1] = a.y;
        u[t * 4 + 2] = a.z; u[t * 4 + 3] = a.w;
    }
    __syncthreads();

    // s[d] = Wq[d,:] . u + bq[d]*V   (2 outputs per warp)
    const float V = misc[0];
#pragma unroll
    for (int d = warp; d < DD; d += 32) {
        float a = 0.f;
#pragma unroll
        for (int e = lane; e < EE; e += 32) a += __ldg(&Wq[d * EE + e]) * u[e];
#pragma unroll
        for (int o = 16; o; o >>= 1) a += __shfl_xor_sync(0xffffffffu, a, o);
        if (lane == 0) sd[d] = a + __ldg(&bq[d]) * V;
    }
    __syncthreads();

    // wv[col] = sum_d Wk[d][col]*s[d] — split over 4 quarters of d, all 1024 threads
    {
        const int col = t & 255;
        const int q   = t >> 8;         // 0..3, d-range [16q, 16q+16)
        float w = 0.f;
#pragma unroll
        for (int i = 0; i < 16; i++) {
            const int d = q * 16 + i;
            w += __ldg(&Wk[d * EE + col]) * sd[d];
        }
        wpart[q * 256 + col] = w;
    }
    if (warp == 31) {  // c = s . bk (runs in parallel with wpart writes)
        float c = sd[lane] * __ldg(&bk[lane]) + sd[lane + 32] * __ldg(&bk[lane + 32]);
#pragma unroll
        for (int o = 16; o; o >>= 1) c += __shfl_xor_sync(0xffffffffu, c, o);
        if (lane == 0) misc[1] = c;
    }
    __syncthreads();

    if (t < 256) {
        wv[t] = (wpart[t] + wpart[256 + t]) + (wpart[512 + t] + wpart[768 + t]);
    }
    __syncthreads();

    // ---- Phase 3: rows from smem cache; 32 warps x 4 rows (no global gather)
    const float4 w0 = ((const float4*)wv)[lane];
    const float4 w1 = ((const float4*)wv)[lane + 32];
    const float  cs = misc[1];
#pragma unroll
    for (int i = 0; i < 4; i++) {
        const int r = warp * 4 + i;
        const float4 a0 = srow[r * 64 + lane];
        const float4 a1 = srow[r * 64 + lane + 32];
        float dot = a0.x * w0.x + a0.y * w0.y + a0.z * w0.z + a0.w * w0.w
                  + a1.x * w1.x + a1.y * w1.y + a1.z * w1.z + a1.w * w1.w;
#pragma unroll
        for (int o = 16; o; o >>= 1) dot += __shfl_xor_sync(0xffffffffu, dot, o);
        if (lane == 0) {
            const float v = sv[r];
            out[b * NN + ch * RPB + r] = v + v * (SCALE * (dot + cs));
        }
    }
}

// ---------------------------------------------------------------------------
extern "C" void kernel_launch(void* const* d_in, const int* in_sizes, int n_in,
                              void* d_out, int out_size) {
    // metadata order: t, val, pos, embed, Wq, bq, Wk, bk
    const int base = n_in - 7;
    const float* val   = (const float*)d_in[base + 0];
    const int*   pos   = (const int*)  d_in[base + 1];
    const float* embed = (const float*)d_in[base + 2];
    const float* Wq    = (const float*)d_in[base + 3];
    const float* bq    = (const float*)d_in[base + 4];
    const float* Wk    = (const float*)d_in[base + 5];
    const float* bk    = (const float*)d_in[base + 6];
    float* out = (float*)d_out;

    cudaFuncSetAttribute(k_fused, cudaFuncAttributeMaxDynamicSharedMemorySize,
                         SMEM_BYTES);
    k_fused<<<NBLK, 1024, SMEM_BYTES>>>(val, pos, embed, Wq, bq, Wk, bk, out);
}